// round 7
// baseline (speedup 1.0000x reference)
#include <cuda_runtime.h>
#include <cuda_fp16.h>
#include <cstdint>

// ---------------------------------------------------------------------------
// Problem constants
// ---------------------------------------------------------------------------
#define THREADS 256
#define F_DIM 160
#define NQ 4096
#define NA 32768
#define NC 10
#define SPLITS 32
#define A_CHUNK 1024          // addresses per CTA
#define TN 64                 // N tile (addresses per tile)
#define NTILES (A_CHUNK / TN) // 16
#define KEXP (-1.31154095f)   // -log2(e)/1.1 : exp(-d/1.1) = 2^(d*KEXP)
#define WSHIFT 24.0f          // softmin-invariant weight scale 2^24
#define TCLAMP 14.0f          // clamp t -> w <= 2^14 (fp16-safe)

// ---------------------------------------------------------------------------
// Shared memory layout
// fp16 X/Y tiles: 336B rows (84 f32-quads: 84*r mod 32 all-distinct -> the
// 8-row ldmatrix groups are bank-conflict-free). Scores: f32, 272B rows
// (68*r mod 32 distinct). Mt: 144B rows.
// ---------------------------------------------------------------------------
#define ROWB 336
#define SROWB 272
#define MTROWB 144
#define OFF_X   0
#define SZ_X    (128 * ROWB)            // 43008
#define OFF_Y0  SZ_X                    // 43008
#define SZ_YBUF (TN * ROWB)             // 21504
#define OFF_Y1  (OFF_Y0 + SZ_YBUF)      // 64512
#define OFF_S   (OFF_Y1 + SZ_YBUF)      // 86016  scores [2][128][68] f32
#define SZ_SBUF (128 * SROWB)           // 34816
#define OFF_MT  (OFF_S + 2 * SZ_SBUF)   // 155648 Mt[16][72] fp16 (M^T + ones)
#define SZ_MT   (16 * MTROWB)           // 2304
#define OFF_Y2S (OFF_MT + SZ_MT)        // 157952 y2 chunk [64] f32
#define OFF_X2S (OFF_Y2S + 256)         // 158208 x2 tile [128] f32
#define SMEM_BYTES (OFF_X2S + 512)      // 158720 (1 CTA/SM)

// ---------------------------------------------------------------------------
// Device scratch
// ---------------------------------------------------------------------------
__device__ __half g_xh[(size_t)NQ * F_DIM];
__device__ __half g_yh[(size_t)NA * F_DIM];
__device__ float g_x2[NQ];
__device__ float g_y2[NA];
__device__ float g_part[(size_t)SPLITS * NQ * 16];  // [split][row][16]: 10 num, den@10

// ---------------------------------------------------------------------------
// PTX helpers
// ---------------------------------------------------------------------------
__device__ __forceinline__ uint32_t cvta_s(const void* p) {
    uint32_t r;
    asm("{ .reg .u64 t; cvta.to.shared.u64 t, %1; cvt.u32.u64 %0, t; }"
        : "=r"(r) : "l"(p));
    return r;
}

#define LDMX4(r, a)                                                            \
    asm volatile("ldmatrix.sync.aligned.m8n8.x4.shared.b16 {%0,%1,%2,%3}, [%4];" \
                 : "=r"((r)[0]), "=r"((r)[1]), "=r"((r)[2]), "=r"((r)[3])      \
                 : "r"(a))

#define MMA_F16(d, a, b0, b1)                                                  \
    asm volatile("mma.sync.aligned.m16n8k16.row.col.f32.f16.f16.f32 "          \
                 "{%0,%1,%2,%3},{%4,%5,%6,%7},{%8,%9},{%0,%1,%2,%3};"          \
                 : "+f"((d)[0]), "+f"((d)[1]), "+f"((d)[2]), "+f"((d)[3])      \
                 : "r"((a)[0]), "r"((a)[1]), "r"((a)[2]), "r"((a)[3]),         \
                   "r"(b0), "r"(b1))

#define CPASYNC16(d, s)                                                        \
    asm volatile("cp.async.cg.shared.global [%0], [%1], 16;" :: "r"(d), "l"(s))
#define CPCOMMIT() asm volatile("cp.async.commit_group;" ::: "memory")
#define CPWAIT1()  asm volatile("cp.async.wait_group 1;" ::: "memory")

#define BAR_SYNC(id, cnt) \
    asm volatile("bar.sync %0, %1;" :: "r"((int)(id)), "r"((int)(cnt)) : "memory")
#define BAR_ARRIVE(id, cnt) \
    asm volatile("bar.arrive %0, %1;" :: "r"((int)(id)), "r"((int)(cnt)) : "memory")
#define MEMBAR_CTA() asm volatile("membar.cta;" ::: "memory")

// cp.async one Y tile (fp16), 128 producer threads: 64 rows x 20 x 16B
__device__ __forceinline__ void issue_y128(int a0row, uint32_t dbase, int tid) {
    const char* gs = (const char*)(g_yh + (size_t)a0row * F_DIM);
    #pragma unroll
    for (int k = 0; k < 10; k++) {
        int i = k * 128 + tid;
        int r = i / 20, c = i - r * 20;
        CPASYNC16(dbase + r * ROWB + c * 16, gs + (size_t)r * 320 + c * 16);
    }
}

// scores pair -> fp16x2 softmin weight pair (one GEMM-2 A-fragment register)
__device__ __forceinline__ uint32_t wpair(float2 s, float x2v, float2 y2) {
    float d2x = fmaxf(fmaf(-2.f, s.x, x2v + y2.x), 0.f);
    float d2y = fmaxf(fmaf(-2.f, s.y, x2v + y2.y), 0.f);
    float dx, dy;
    asm("sqrt.approx.ftz.f32 %0, %1;" : "=f"(dx) : "f"(d2x));
    asm("sqrt.approx.ftz.f32 %0, %1;" : "=f"(dy) : "f"(d2y));
    float tx = fminf(fmaf(KEXP, dx, WSHIFT), TCLAMP);
    float ty = fminf(fmaf(KEXP, dy, WSHIFT), TCLAMP);
    __half2 th = __floats2half2_rn(tx, ty);
    uint32_t w;
    asm("ex2.approx.f16x2 %0, %1;" : "=r"(w) : "r"(*(uint32_t*)&th));
    return w;
}

// ---------------------------------------------------------------------------
// Kernel 0: exact fp32 row norms + fp16 conversion
// ---------------------------------------------------------------------------
__global__ void norms_kernel(const float* __restrict__ X, const float* __restrict__ Y) {
    int gw = (int)((blockIdx.x * blockDim.x + threadIdx.x) >> 5);
    int lane = threadIdx.x & 31;
    const float4* src;
    uint2* dsth;
    float* dst;
    if (gw < NQ) {
        src = (const float4*)(X + (size_t)gw * F_DIM);
        dsth = (uint2*)(g_xh + (size_t)gw * F_DIM); dst = g_x2 + gw;
    } else if (gw < NQ + NA) {
        int r = gw - NQ;
        src = (const float4*)(Y + (size_t)r * F_DIM);
        dsth = (uint2*)(g_yh + (size_t)r * F_DIM); dst = g_y2 + r;
    } else return;
    float s = 0.f;
    #pragma unroll
    for (int k = 0; k < 2; k++) {
        int j = lane + k * 32;
        if (k == 0 || j < 40) {
            float4 v = src[j];
            s = fmaf(v.x, v.x, s); s = fmaf(v.y, v.y, s);
            s = fmaf(v.z, v.z, s); s = fmaf(v.w, v.w, s);
            __half2 h0 = __floats2half2_rn(v.x, v.y);
            __half2 h1 = __floats2half2_rn(v.z, v.w);
            uint2 u;
            u.x = *(uint32_t*)&h0; u.y = *(uint32_t*)&h1;
            dsth[j] = u;
        }
    }
    #pragma unroll
    for (int o = 16; o > 0; o >>= 1) s += __shfl_xor_sync(0xFFFFFFFFu, s, o);
    if (lane == 0) *dst = s;
}

// ---------------------------------------------------------------------------
// Kernel 1: warp-specialized fused kernel.
// Warps 0-3 (producers): GEMM-1 fp16 mma -> f32 scores to smem (2 buffers).
// Warps 4-7 (consumers): scores -> sqrt/ex2 weights packed as mma A-frags in
// registers -> GEMM-2 against Mt -> per-split partials.
// Named bars: 1/2 = S[b] full (P arrive, C sync); 3/4 = S[b] free (C arrive,
// P sync); 5 = producer-only; 6 = consumer-only. grid = 1024, 1 CTA/SM.
// ---------------------------------------------------------------------------
__global__ void __launch_bounds__(THREADS, 1) fused_kernel(
    const float* __restrict__ Mv)
{
    extern __shared__ __align__(1024) char sm[];
    const uint32_t sb = cvta_s(sm);
    const int tid  = threadIdx.x;
    const int lane = tid & 31, warp = tid >> 5;
    const int g = lane >> 2, tig = lane & 3;
    const int m_tile = (int)blockIdx.x >> 5;
    const int split  = (int)blockIdx.x & (SPLITS - 1);
    const int a_start = split * A_CHUNK;
    const int lrow = (lane & 7) + ((lane >> 3) & 1) * 8;
    const int lcol = ((lane >> 4) & 1) * 16;

    // --- prologue (all 256 threads) -------------------------------------
    if (tid < 128) {
        issue_y128(a_start, sb + OFF_Y0, tid); CPCOMMIT();
        issue_y128(a_start + TN, sb + OFF_Y1, tid); CPCOMMIT();
    }
    {
        const char* xg = (const char*)(g_xh + (size_t)m_tile * 128 * F_DIM);
        #pragma unroll
        for (int k = 0; k < 10; k++) {
            int i = k * THREADS + tid;
            int r = i / 20, c = i - r * 20;
            *(uint4*)(sm + OFF_X + r * ROWB + c * 16) =
                *(const uint4*)(xg + (size_t)r * 320 + c * 16);
        }
    }
    if (tid < 128) ((float*)(sm + OFF_X2S))[tid] = g_x2[m_tile * 128 + tid];
    {   // Mt rows 10..15: ones column (den) then zeros (written once)
        __half one = __float2half(1.0f);
        __half zro = __float2half(0.0f);
        for (int i = tid; i < 6 * TN; i += THREADS) {
            int c = 10 + i / TN, j = i - (c - 10) * TN;
            *(__half*)(sm + OFF_MT + c * MTROWB + j * 2) = (c == 10) ? one : zro;
        }
    }
    __syncthreads();

    if (warp < 4) {
        // ================= PRODUCER: GEMM-1 ==============================
        uint32_t aA[2];
        #pragma unroll
        for (int mf = 0; mf < 2; mf++)
            aA[mf] = sb + OFF_X + (warp * 32 + mf * 16 + lrow) * ROWB + lcol;
        uint32_t bBo[4];
        #pragma unroll
        for (int j = 0; j < 4; j++)
            bBo[j] = (uint32_t)((j * 16 + lrow) * ROWB + lcol);

        for (int t = 0; t < NTILES; t++) {
            CPWAIT1();
            BAR_SYNC(5, 128);               // Y[t&1] visible to all producers

            float acc[2][8][4];
            #pragma unroll
            for (int mf = 0; mf < 2; mf++)
                #pragma unroll
                for (int nf = 0; nf < 8; nf++)
                    #pragma unroll
                    for (int q = 0; q < 4; q++) acc[mf][nf][q] = 0.f;

            const uint32_t yB = sb + OFF_Y0 + (t & 1) * SZ_YBUF;
            #pragma unroll
            for (int ks = 0; ks < 10; ks++) {
                uint32_t afr[2][4], bfr[4][4];
                #pragma unroll
                for (int mf = 0; mf < 2; mf++)
                    LDMX4(afr[mf], aA[mf] + ks * 32);
                #pragma unroll
                for (int j = 0; j < 4; j++)
                    LDMX4(bfr[j], yB + bBo[j] + ks * 32);
                #pragma unroll
                for (int mf = 0; mf < 2; mf++)
                    #pragma unroll
                    for (int j = 0; j < 4; j++) {
                        MMA_F16(acc[mf][j * 2],     afr[mf], bfr[j][0], bfr[j][2]);
                        MMA_F16(acc[mf][j * 2 + 1], afr[mf], bfr[j][1], bfr[j][3]);
                    }
            }
            BAR_SYNC(5, 128);               // all producers done reading Y[t&1]
            if (t + 2 < NTILES)
                issue_y128(a_start + (t + 2) * TN, sb + OFF_Y0 + (t & 1) * SZ_YBUF, tid);
            CPCOMMIT();

            if (t >= 2) BAR_SYNC(3 + (t & 1), 256);   // S[t&1] free
            {
                char* Sb = sm + OFF_S + (t & 1) * SZ_SBUF;
                #pragma unroll
                for (int mf = 0; mf < 2; mf++) {
                    int row0 = warp * 32 + mf * 16 + g;
                    #pragma unroll
                    for (int nf = 0; nf < 8; nf++) {
                        int colb = (nf * 8 + tig * 2) * 4;
                        *(float2*)(Sb + row0 * SROWB + colb) =
                            make_float2(acc[mf][nf][0], acc[mf][nf][1]);
                        *(float2*)(Sb + (row0 + 8) * SROWB + colb) =
                            make_float2(acc[mf][nf][2], acc[mf][nf][3]);
                    }
                }
            }
            MEMBAR_CTA();
            BAR_ARRIVE(1 + (t & 1), 256);   // S[t&1] full
        }
    } else {
        // ================= CONSUMER: epilogue + GEMM-2 ===================
        const int cw = warp - 4;
        const int tid2 = tid - 128;
        const uint32_t bMb = sb + OFF_MT + lrow * MTROWB + lcol;
        float x2c[2][2];
        {
            const float* x2s = (const float*)(sm + OFF_X2S);
            #pragma unroll
            for (int mf = 0; mf < 2; mf++) {
                x2c[mf][0] = x2s[cw * 32 + mf * 16 + g];
                x2c[mf][1] = x2s[cw * 32 + mf * 16 + g + 8];
            }
        }
        float acc2[2][2][4];
        #pragma unroll
        for (int mf = 0; mf < 2; mf++)
            #pragma unroll
            for (int n = 0; n < 2; n++)
                #pragma unroll
                for (int q = 0; q < 4; q++) acc2[mf][n][q] = 0.f;

        for (int t = 0; t < NTILES; t++) {
            // prefetch M tile (64x10) + y2 chunk while waiting
            float mv[5];
            float y2v = 0.f;
            #pragma unroll
            for (int k = 0; k < 5; k++) {
                int i = k * 128 + tid2;
                if (i < TN * NC) {
                    int j = i / 10, c = i - j * 10;
                    mv[k] = Mv[(size_t)(a_start + t * TN + j) * NC + c];
                }
            }
            if (tid2 < TN) y2v = g_y2[a_start + t * TN + tid2];

            BAR_SYNC(1 + (t & 1), 256);     // S[t&1] full
            BAR_SYNC(6, 128);               // prev GEMM-2 done with Mt
            #pragma unroll
            for (int k = 0; k < 5; k++) {
                int i = k * 128 + tid2;
                if (i < TN * NC) {
                    int j = i / 10, c = i - j * 10;
                    *(__half*)(sm + OFF_MT + c * MTROWB + j * 2) = __float2half_rn(mv[k]);
                }
            }
            if (tid2 < TN) ((float*)(sm + OFF_Y2S))[tid2] = y2v;
            BAR_SYNC(6, 128);               // Mt/y2 visible

            const char* Sb = sm + OFF_S + (t & 1) * SZ_SBUF;
            #pragma unroll
            for (int k2 = 0; k2 < 4; k2++) {
                uint32_t bm[4];
                LDMX4(bm, bMb + k2 * 32);
                const int c2 = k2 * 16 + tig * 2;
                float2 y2a = *(const float2*)(sm + OFF_Y2S + c2 * 4);
                float2 y2b = *(const float2*)(sm + OFF_Y2S + (c2 + 8) * 4);
                #pragma unroll
                for (int mf = 0; mf < 2; mf++) {
                    int row0 = cw * 32 + mf * 16 + g;
                    float2 s00 = *(const float2*)(Sb + row0 * SROWB + c2 * 4);
                    float2 s10 = *(const float2*)(Sb + (row0 + 8) * SROWB + c2 * 4);
                    float2 s01 = *(const float2*)(Sb + row0 * SROWB + (c2 + 8) * 4);
                    float2 s11 = *(const float2*)(Sb + (row0 + 8) * SROWB + (c2 + 8) * 4);
                    uint32_t af[4];
                    af[0] = wpair(s00, x2c[mf][0], y2a);
                    af[1] = wpair(s10, x2c[mf][1], y2a);
                    af[2] = wpair(s01, x2c[mf][0], y2b);
                    af[3] = wpair(s11, x2c[mf][1], y2b);
                    MMA_F16(acc2[mf][0], af, bm[0], bm[2]);
                    MMA_F16(acc2[mf][1], af, bm[1], bm[3]);
                }
            }
            BAR_ARRIVE(3 + (t & 1), 256);   // S[t&1] free
        }

        // --- write per-split partials ------------------------------------
        #pragma unroll
        for (int mf = 0; mf < 2; mf++) {
            int r0 = m_tile * 128 + cw * 32 + mf * 16 + g;
            size_t base = ((size_t)split * NQ + r0) * 16 + tig * 2;
            #pragma unroll
            for (int n = 0; n < 2; n++) {
                *(float2*)&g_part[base + n * 8] =
                    make_float2(acc2[mf][n][0], acc2[mf][n][1]);
                *(float2*)&g_part[base + 8 * 16 + n * 8] =
                    make_float2(acc2[mf][n][2], acc2[mf][n][3]);
            }
        }
    }
}

// ---------------------------------------------------------------------------
// Kernel 2: combine splits, normalize
// ---------------------------------------------------------------------------
__global__ void combine_kernel(float* __restrict__ out) {
    __shared__ float dsh[16];
    int tid = threadIdx.x;
    int il = tid >> 4, c = tid & 15;
    int i = blockIdx.x * 16 + il;
    float s = 0.f;
    #pragma unroll 4
    for (int sp = 0; sp < SPLITS; sp++)
        s += g_part[((size_t)sp * NQ + i) * 16 + c];
    if (c == 10) dsh[il] = s;
    __syncthreads();
    if (c < 10) out[(size_t)i * NC + c] = s / dsh[il];
}

// ---------------------------------------------------------------------------
// kernel_launch
// ---------------------------------------------------------------------------
extern "C" void kernel_launch(void* const* d_in, const int* in_sizes, int n_in,
                              void* d_out, int out_size) {
    const float* X  = (const float*)d_in[0];   // inputs  [4096, 160]
    const float* Y  = (const float*)d_in[1];   // Address [32768, 160]
    const float* Mv = (const float*)d_in[2];   // M       [32768, 10]
    float* out = (float*)d_out;                // [4096, 10]

    static bool attr_done = false;
    if (!attr_done) {
        cudaFuncSetAttribute(fused_kernel,
                             cudaFuncAttributeMaxDynamicSharedMemorySize, SMEM_BYTES);
        attr_done = true;
    }

    int norm_warps = NQ + NA;
    norms_kernel<<<(norm_warps * 32 + 255) / 256, 256>>>(X, Y);
    fused_kernel<<<(NQ / 128) * SPLITS, THREADS, SMEM_BYTES>>>(Mv);
    combine_kernel<<<NQ / 16, 256>>>(out);
}

// round 8
// speedup vs baseline: 1.2104x; 1.2104x over previous
#include <cuda_runtime.h>
#include <cuda_fp16.h>
#include <cstdint>

// ---------------------------------------------------------------------------
// Problem constants
// ---------------------------------------------------------------------------
#define THREADS 256
#define F_DIM 160
#define NQ 4096
#define NA 32768
#define NC 10
#define SPLITS 32
#define A_CHUNK 1024          // addresses per CTA
#define TN 64                 // N tile (addresses per tile)
#define NTILES (A_CHUNK / TN) // 16
#define KSTEPS 5              // 160 fp8 bytes / 32 per mma
#define KEXP (-1.31154095f)   // -log2(e)/1.1 : exp(-d/1.1) = 2^(d*KEXP)
#define WSHIFT 24.0f          // softmin-invariant weight scale 2^24
#define TCLAMP 14.0f          // clamp t -> w <= 2^14 (fp16-safe)

// ---------------------------------------------------------------------------
// Shared memory layout. fp8 X/Y tiles: 160B rows padded to 176B
// (176 mod 128 = 48; 48*r mod 128 distinct for r=0..7 -> ldmatrix 8-row
// groups bank-conflict-free). W fp16 144B rows, Mt 144B rows.
// ---------------------------------------------------------------------------
#define ROWB 176
#define WROWB 144                      // 72 fp16 (64 used)
#define MTROWB 144
#define OFF_X   0
#define SZ_X    (128 * ROWB)           // 22528
#define OFF_Y0  SZ_X                   // 22528
#define SZ_YBUF (TN * ROWB)            // 11264
#define OFF_Y1  (OFF_Y0 + SZ_YBUF)     // 33792
#define OFF_W   (OFF_Y1 + SZ_YBUF)     // 45056
#define SZ_W    (128 * WROWB)          // 18432
#define OFF_MT  (OFF_W + SZ_W)         // 63488  Mt[16][72] fp16 (M^T + ones)
#define SZ_MT   (16 * MTROWB)          // 2304
#define OFF_Y2S (OFF_MT + SZ_MT)       // 65792  y2 chunk [64] f32
#define OFF_X2S (OFF_Y2S + 256)        // 66048  x2 tile [128] f32
#define SMEM_BYTES (OFF_X2S + 512)     // 66560  (x2 CTAs -> 133KB/SM)

// ---------------------------------------------------------------------------
// Device scratch
// ---------------------------------------------------------------------------
__device__ uint8_t g_x8[(size_t)NQ * F_DIM];   // e4m3
__device__ uint8_t g_y8[(size_t)NA * F_DIM];   // e4m3
__device__ float g_x2[NQ];
__device__ float g_y2[NA];
__device__ float g_part[(size_t)SPLITS * NQ * 16];  // [split][row][16]: 10 num, den@10

// ---------------------------------------------------------------------------
// PTX helpers
// ---------------------------------------------------------------------------
__device__ __forceinline__ uint32_t cvta_s(const void* p) {
    uint32_t r;
    asm("{ .reg .u64 t; cvta.to.shared.u64 t, %1; cvt.u32.u64 %0, t; }"
        : "=r"(r) : "l"(p));
    return r;
}

#define LDMX4(r, a)                                                            \
    asm volatile("ldmatrix.sync.aligned.m8n8.x4.shared.b16 {%0,%1,%2,%3}, [%4];" \
                 : "=r"((r)[0]), "=r"((r)[1]), "=r"((r)[2]), "=r"((r)[3])      \
                 : "r"(a))

// fp8 e4m3 MMA, K=32 per instruction
#define MMA_FP8(d, a, b0, b1)                                                  \
    asm volatile("mma.sync.aligned.m16n8k32.row.col.f32.e4m3.e4m3.f32 "        \
                 "{%0,%1,%2,%3},{%4,%5,%6,%7},{%8,%9},{%0,%1,%2,%3};"          \
                 : "+f"((d)[0]), "+f"((d)[1]), "+f"((d)[2]), "+f"((d)[3])      \
                 : "r"((a)[0]), "r"((a)[1]), "r"((a)[2]), "r"((a)[3]),         \
                   "r"(b0), "r"(b1))

#define MMA_F16(d, a, b0, b1)                                                  \
    asm volatile("mma.sync.aligned.m16n8k16.row.col.f32.f16.f16.f32 "          \
                 "{%0,%1,%2,%3},{%4,%5,%6,%7},{%8,%9},{%0,%1,%2,%3};"          \
                 : "+f"((d)[0]), "+f"((d)[1]), "+f"((d)[2]), "+f"((d)[3])      \
                 : "r"((a)[0]), "r"((a)[1]), "r"((a)[2]), "r"((a)[3]),         \
                   "r"(b0), "r"(b1))

#define CPASYNC16(d, s)                                                        \
    asm volatile("cp.async.cg.shared.global [%0], [%1], 16;" :: "r"(d), "l"(s))
#define CPCOMMIT() asm volatile("cp.async.commit_group;" ::: "memory")
#define CPWAIT1()  asm volatile("cp.async.wait_group 1;" ::: "memory")

// issue cp.async for one Y tile (fp8): 64 rows x 160B = 640 x 16B
__device__ __forceinline__ void issue_y(int a0row, uint32_t dbase, int tid) {
    const char* gs = (const char*)(g_y8 + (size_t)a0row * F_DIM);
    #pragma unroll
    for (int k = 0; k < 3; k++) {
        int i = k * THREADS + tid;
        if (k < 2 || i < 640) {
            int r = i / 10, c = i - r * 10;
            CPASYNC16(dbase + r * ROWB + c * 16, gs + (size_t)r * 160 + c * 16);
        }
    }
}

// ---------------------------------------------------------------------------
// Kernel 0: exact fp32 row norms + e4m3 conversion
// ---------------------------------------------------------------------------
__global__ void norms_kernel(const float* __restrict__ X, const float* __restrict__ Y) {
    int gw = (int)((blockIdx.x * blockDim.x + threadIdx.x) >> 5);
    int lane = threadIdx.x & 31;
    const float4* src;
    uint32_t* dst8;
    float* dst;
    if (gw < NQ) {
        src = (const float4*)(X + (size_t)gw * F_DIM);
        dst8 = (uint32_t*)(g_x8 + (size_t)gw * F_DIM); dst = g_x2 + gw;
    } else if (gw < NQ + NA) {
        int r = gw - NQ;
        src = (const float4*)(Y + (size_t)r * F_DIM);
        dst8 = (uint32_t*)(g_y8 + (size_t)r * F_DIM); dst = g_y2 + r;
    } else return;
    float s = 0.f;
    #pragma unroll
    for (int k = 0; k < 2; k++) {
        int j = lane + k * 32;
        if (k == 0 || j < 40) {
            float4 v = src[j];
            s = fmaf(v.x, v.x, s); s = fmaf(v.y, v.y, s);
            s = fmaf(v.z, v.z, s); s = fmaf(v.w, v.w, s);
            uint16_t p0, p1;   // e4m3x2: low byte = second operand
            asm("cvt.rn.satfinite.e4m3x2.f32 %0, %1, %2;" : "=h"(p0) : "f"(v.y), "f"(v.x));
            asm("cvt.rn.satfinite.e4m3x2.f32 %0, %1, %2;" : "=h"(p1) : "f"(v.w), "f"(v.z));
            dst8[j] = (uint32_t)p0 | ((uint32_t)p1 << 16);
        }
    }
    #pragma unroll
    for (int o = 16; o > 0; o >>= 1) s += __shfl_xor_sync(0xFFFFFFFFu, s, o);
    if (lane == 0) *dst = s;
}

// ---------------------------------------------------------------------------
// Kernel 1: fused scores(e4m3 mma) -> shifted softmin weights (fp16) -> W@[M|1]
// grid = 32 m-tiles x 32 A-splits; 256 threads; 2 CTAs/SM
// GEMM-1 warp grid 4(m) x 2(n); warp tile 32x32
// ---------------------------------------------------------------------------
__global__ void __launch_bounds__(THREADS, 2) fused_kernel(
    const float* __restrict__ Mv)
{
    extern __shared__ __align__(1024) char sm[];
    const uint32_t sb = cvta_s(sm);
    const int tid  = threadIdx.x;
    const int lane = tid & 31, warp = tid >> 5;
    const int mw = warp >> 1, nw = warp & 1;
    const int g = lane >> 2, tig = lane & 3;
    const int m_tile = (int)blockIdx.x >> 5;
    const int split  = (int)blockIdx.x & (SPLITS - 1);
    const int a_start = split * A_CHUNK;

    // --- prologue: async-load Y tiles 0 and 1 ---------------------------
    issue_y(a_start, sb + OFF_Y0, tid); CPCOMMIT();
    issue_y(a_start + TN, sb + OFF_Y1, tid); CPCOMMIT();

    // --- X tile (fp8, once per CTA), x2 chunk, constant Mt rows ---------
    {
        const char* xg = (const char*)(g_x8 + (size_t)m_tile * 128 * F_DIM);
        #pragma unroll
        for (int k = 0; k < 5; k++) {
            int i = k * THREADS + tid;   // 1280 = 128 rows x 10 x 16B
            int r = i / 10, c = i - r * 10;
            *(uint4*)(sm + OFF_X + r * ROWB + c * 16) =
                *(const uint4*)(xg + (size_t)r * 160 + c * 16);
        }
    }
    if (tid < 128) ((float*)(sm + OFF_X2S))[tid] = g_x2[m_tile * 128 + tid];
    {   // Mt rows 10..15: ones column (den), zeros elsewhere (written once)
        __half one = __float2half(1.0f);
        __half zro = __float2half(0.0f);
        for (int i = tid; i < 6 * TN; i += THREADS) {
            int c = 10 + i / TN, j = i - (c - 10) * TN;
            *(__half*)(sm + OFF_MT + c * MTROWB + j * 2) = (c == 10) ? one : zro;
        }
    }
    __syncthreads();

    // --- per-thread ldmatrix bases --------------------------------------
    const int lrow = (lane & 7) + ((lane >> 3) & 1) * 8;
    const int lcol = ((lane >> 4) & 1) * 16;      // 16B half within 32B k-step
    uint32_t aA[2];
    #pragma unroll
    for (int mf = 0; mf < 2; mf++)
        aA[mf] = sb + OFF_X + (mw * 32 + mf * 16 + lrow) * ROWB + lcol;
    uint32_t bBo[2];
    #pragma unroll
    for (int p = 0; p < 2; p++)
        bBo[p] = (uint32_t)((nw * 32 + p * 16 + lrow) * ROWB + lcol);
    const uint32_t aWb = sb + OFF_W + (warp * 16 + lrow) * WROWB + lcol;
    const uint32_t bMb = sb + OFF_MT + lrow * MTROWB + lcol;

    float x2a[4];   // rows mw*32 + mf*16 + (q>>1)*8 + g
    {
        const float* x2s = (const float*)(sm + OFF_X2S);
        #pragma unroll
        for (int q = 0; q < 4; q++)
            x2a[q] = x2s[mw * 32 + (q >> 1) * 16 + (q & 1) * 8 + g];
    }

    float acc2[2][4] = {{0.f, 0.f, 0.f, 0.f}, {0.f, 0.f, 0.f, 0.f}};
    float acc[2][4][4];

    for (int t = 0; t < NTILES; t++) {
        // prefetch next M tile (64x10) + y2 chunk into registers
        float mv[3];
        float y2v = 0.f;
        #pragma unroll
        for (int k = 0; k < 3; k++) {
            int i = k * THREADS + tid;
            if (i < TN * NC) {
                int j = i / 10, c = i - j * 10;
                mv[k] = Mv[(size_t)(a_start + t * TN + j) * NC + c];
            }
        }
        if (tid < TN) y2v = g_y2[a_start + t * TN + tid];
        #pragma unroll
        for (int mf = 0; mf < 2; mf++)
            #pragma unroll
            for (int nf = 0; nf < 4; nf++)
                #pragma unroll
                for (int q = 0; q < 4; q++) acc[mf][nf][q] = 0.f;

        CPWAIT1();              // Y buffer [t&1] ready
        __syncthreads();        // + prev GEMM-2 done reading W/Mt

        // ---- GEMM-1: 5 e4m3 K-steps (K=32 bytes each), 8 MMA per step ---
        {
            const uint32_t yB = sb + OFF_Y0 + (t & 1) * SZ_YBUF;
            #pragma unroll
            for (int ks = 0; ks < KSTEPS; ks++) {
                uint32_t afr[2][4], bfr[2][4];
                #pragma unroll
                for (int mf = 0; mf < 2; mf++)
                    LDMX4(afr[mf], aA[mf] + ks * 32);
                #pragma unroll
                for (int p = 0; p < 2; p++)
                    LDMX4(bfr[p], yB + bBo[p] + ks * 32);
                #pragma unroll
                for (int mf = 0; mf < 2; mf++)
                    #pragma unroll
                    for (int p = 0; p < 2; p++) {
                        MMA_FP8(acc[mf][p * 2],     afr[mf], bfr[p][0], bfr[p][2]);
                        MMA_FP8(acc[mf][p * 2 + 1], afr[mf], bfr[p][1], bfr[p][3]);
                    }
            }
        }
        // publish Mt (fp16, transposed) + y2 chunk
        #pragma unroll
        for (int k = 0; k < 3; k++) {
            int i = k * THREADS + tid;
            if (i < TN * NC) {
                int j = i / 10, c = i - j * 10;
                *(__half*)(sm + OFF_MT + c * MTROWB + j * 2) = __float2half_rn(mv[k]);
            }
        }
        if (tid < TN) ((float*)(sm + OFF_Y2S))[tid] = y2v;
        __syncthreads();        // Y buf consumed; Mt/y2 visible

        if (t + 2 < NTILES) issue_y(a_start + (t + 2) * TN, sb + OFF_Y0 + (t & 1) * SZ_YBUF, tid);
        CPCOMMIT();

        // ---- epilogue: d2 -> sqrt -> t=KEXP*d+S -> ex2.f16x2 -> W fp16 ---
        {
            const float* y2s = (const float*)(sm + OFF_Y2S);
            float y2l[8];
            #pragma unroll
            for (int nf = 0; nf < 4; nf++) {
                y2l[nf * 2]     = y2s[nw * 32 + nf * 8 + tig * 2];
                y2l[nf * 2 + 1] = y2s[nw * 32 + nf * 8 + tig * 2 + 1];
            }
            #pragma unroll
            for (int mf = 0; mf < 2; mf++) {
                #pragma unroll
                for (int nf = 0; nf < 4; nf++) {
                    float tt[4];
                    #pragma unroll
                    for (int q = 0; q < 4; q++) {
                        float d2 = fmaf(-2.f, acc[mf][nf][q],
                                        x2a[mf * 2 + (q >> 1)] + y2l[nf * 2 + (q & 1)]);
                        d2 = fmaxf(d2, 0.f);
                        float d;
                        asm("sqrt.approx.ftz.f32 %0, %1;" : "=f"(d) : "f"(d2));
                        tt[q] = fminf(fmaf(KEXP, d, WSHIFT), TCLAMP);
                    }
                    __half2 t0 = __floats2half2_rn(tt[0], tt[1]);
                    __half2 t1 = __floats2half2_rn(tt[2], tt[3]);
                    uint32_t w0, w1;
                    asm("ex2.approx.f16x2 %0, %1;" : "=r"(w0) : "r"(*(uint32_t*)&t0));
                    asm("ex2.approx.f16x2 %0, %1;" : "=r"(w1) : "r"(*(uint32_t*)&t1));
                    int colb = (nw * 32 + nf * 8 + tig * 2) * 2;
                    int r0 = mw * 32 + mf * 16 + g;
                    *(uint32_t*)(sm + OFF_W + r0 * WROWB + colb) = w0;
                    *(uint32_t*)(sm + OFF_W + (r0 + 8) * WROWB + colb) = w1;
                }
            }
        }
        __syncthreads();        // W tile complete
        // ---- GEMM-2: acc2 += W[128x64] @ Mt^T[64x16] (fp16) --------------
        #pragma unroll
        for (int k2 = 0; k2 < 4; k2++) {
            uint32_t aw[4], bm[4];
            LDMX4(aw, aWb + k2 * 32);
            LDMX4(bm, bMb + k2 * 32);
            MMA_F16(acc2[0], aw, bm[0], bm[2]);
            MMA_F16(acc2[1], aw, bm[1], bm[3]);
        }
    }

    // --- write per-split partials ---------------------------------------
    {
        int r0 = m_tile * 128 + warp * 16 + g;
        size_t base = ((size_t)split * NQ + r0) * 16 + tig * 2;
        #pragma unroll
        for (int nf = 0; nf < 2; nf++) {
            *(float2*)&g_part[base + nf * 8]          = make_float2(acc2[nf][0], acc2[nf][1]);
            *(float2*)&g_part[base + 8 * 16 + nf * 8] = make_float2(acc2[nf][2], acc2[nf][3]);
        }
    }
}

// ---------------------------------------------------------------------------
// Kernel 2: combine splits, normalize
// ---------------------------------------------------------------------------
__global__ void combine_kernel(float* __restrict__ out) {
    __shared__ float dsh[16];
    int tid = threadIdx.x;
    int il = tid >> 4, c = tid & 15;
    int i = blockIdx.x * 16 + il;
    float s = 0.f;
    #pragma unroll 4
    for (int sp = 0; sp < SPLITS; sp++)
        s += g_part[((size_t)sp * NQ + i) * 16 + c];
    if (c == 10) dsh[il] = s;
    __syncthreads();
    if (c < 10) out[(size_t)i * NC + c] = s / dsh[il];
}

// ---------------------------------------------------------------------------
// kernel_launch
// ---------------------------------------------------------------------------
extern "C" void kernel_launch(void* const* d_in, const int* in_sizes, int n_in,
                              void* d_out, int out_size) {
    const float* X  = (const float*)d_in[0];   // inputs  [4096, 160]
    const float* Y  = (const float*)d_in[1];   // Address [32768, 160]
    const float* Mv = (const float*)d_in[2];   // M       [32768, 10]
    float* out = (float*)d_out;                // [4096, 10]

    static bool attr_done = false;
    if (!attr_done) {
        cudaFuncSetAttribute(fused_kernel,
                             cudaFuncAttributeMaxDynamicSharedMemorySize, SMEM_BYTES);
        attr_done = true;
    }

    int norm_warps = NQ + NA;
    norms_kernel<<<(norm_warps * 32 + 255) / 256, 256>>>(X, Y);
    fused_kernel<<<(NQ / 128) * SPLITS, THREADS, SMEM_BYTES>>>(Mv);
    combine_kernel<<<NQ / 16, 256>>>(out);
}

// round 9
// speedup vs baseline: 1.2581x; 1.0394x over previous
#include <cuda_runtime.h>
#include <cuda_fp16.h>
#include <cstdint>

// ---------------------------------------------------------------------------
// Problem constants
// ---------------------------------------------------------------------------
#define THREADS 256
#define F_DIM 160
#define NQ 4096
#define NA 32768
#define NC 10
#define SPLITS 32
#define A_CHUNK 1024          // addresses per CTA
#define TN 64                 // N tile (addresses per tile)
#define NTILES (A_CHUNK / TN) // 16
#define KEXP (-1.31154095f)   // -log2(e)/1.1 : exp(-d/1.1) = 2^(d*KEXP)
#define WSHIFT 24.0f          // softmin-invariant weight scale 2^24
#define TCLAMP 14.0f          // clamp t -> w <= 2^14 (fp16-safe)

// ---------------------------------------------------------------------------
// Shared memory layout (fp16 tiles, 336B row stride: 84*r mod 32 distinct
// bank quads for 8-row ldmatrix groups -> conflict-free; 144B likewise).
// No W tile: GEMM-2 A-operand lives in registers.
// ---------------------------------------------------------------------------
#define ROWB 336
#define MTROWB 144
#define OFF_X   0
#define SZ_X    (128 * ROWB)           // 43008
#define OFF_Y0  SZ_X                   // 43008
#define SZ_YBUF (TN * ROWB)            // 21504
#define OFF_Y1  (OFF_Y0 + SZ_YBUF)     // 64512
#define OFF_MT  (OFF_Y1 + SZ_YBUF)     // 86016  Mt[16][72] fp16 (M^T + ones)
#define SZ_MT   (16 * MTROWB)          // 2304
#define OFF_Y2S (OFF_MT + SZ_MT)       // 88320  y2 chunk [64] f32
#define OFF_X2S (OFF_Y2S + 256)        // 88576  x2 tile [128] f32
#define SMEM_BYTES (OFF_X2S + 512)     // 89088  (x2 CTAs -> 178KB/SM)

// ---------------------------------------------------------------------------
// Device scratch
// ---------------------------------------------------------------------------
__device__ __half g_xh[(size_t)NQ * F_DIM];
__device__ __half g_yh[(size_t)NA * F_DIM];
__device__ float g_x2[NQ];
__device__ float g_y2[NA];
__device__ float g_part[(size_t)SPLITS * NQ * 16];  // [split][row][16]: 10 num, den@10

// ---------------------------------------------------------------------------
// PTX helpers
// ---------------------------------------------------------------------------
__device__ __forceinline__ uint32_t cvta_s(const void* p) {
    uint32_t r;
    asm("{ .reg .u64 t; cvta.to.shared.u64 t, %1; cvt.u32.u64 %0, t; }"
        : "=r"(r) : "l"(p));
    return r;
}

#define LDMX4(r, a)                                                            \
    asm volatile("ldmatrix.sync.aligned.m8n8.x4.shared.b16 {%0,%1,%2,%3}, [%4];" \
                 : "=r"((r)[0]), "=r"((r)[1]), "=r"((r)[2]), "=r"((r)[3])      \
                 : "r"(a))

#define MMA_F16(d, a, b0, b1)                                                  \
    asm volatile("mma.sync.aligned.m16n8k16.row.col.f32.f16.f16.f32 "          \
                 "{%0,%1,%2,%3},{%4,%5,%6,%7},{%8,%9},{%0,%1,%2,%3};"          \
                 : "+f"((d)[0]), "+f"((d)[1]), "+f"((d)[2]), "+f"((d)[3])      \
                 : "r"((a)[0]), "r"((a)[1]), "r"((a)[2]), "r"((a)[3]),         \
                   "r"(b0), "r"(b1))

#define CPASYNC16(d, s)                                                        \
    asm volatile("cp.async.cg.shared.global [%0], [%1], 16;" :: "r"(d), "l"(s))
#define CPCOMMIT() asm volatile("cp.async.commit_group;" ::: "memory")
#define CPWAIT1()  asm volatile("cp.async.wait_group 1;" ::: "memory")

// issue cp.async for one Y tile (fp16): rows [a0row, a0row+64), 320B/row
__device__ __forceinline__ void issue_y(int a0row, uint32_t dbase, int tid) {
    const char* gs = (const char*)(g_yh + (size_t)a0row * F_DIM);
    #pragma unroll
    for (int k = 0; k < 5; k++) {
        int i = k * THREADS + tid;        // 64 rows x 20 x 16B
        int r = i / 20, c = i - r * 20;
        CPASYNC16(dbase + r * ROWB + c * 16, gs + (size_t)r * 320 + c * 16);
    }
}

// two f32 scores -> fp16x2 softmin-weight pair (one GEMM-2 A-fragment reg)
__device__ __forceinline__ uint32_t wpair2(float s0, float s1, float x2v, float2 y2) {
    float d20 = fmaxf(fmaf(-2.f, s0, x2v + y2.x), 0.f);
    float d21 = fmaxf(fmaf(-2.f, s1, x2v + y2.y), 0.f);
    float d0, d1;
    asm("sqrt.approx.ftz.f32 %0, %1;" : "=f"(d0) : "f"(d20));
    asm("sqrt.approx.ftz.f32 %0, %1;" : "=f"(d1) : "f"(d21));
    float t0 = fminf(fmaf(KEXP, d0, WSHIFT), TCLAMP);
    float t1 = fminf(fmaf(KEXP, d1, WSHIFT), TCLAMP);
    __half2 th = __floats2half2_rn(t0, t1);
    uint32_t w;
    asm("ex2.approx.f16x2 %0, %1;" : "=r"(w) : "r"(*(uint32_t*)&th));
    return w;
}

// ---------------------------------------------------------------------------
// Kernel 0: exact fp32 row norms + fp16 conversion
// ---------------------------------------------------------------------------
__global__ void norms_kernel(const float* __restrict__ X, const float* __restrict__ Y) {
    int gw = (int)((blockIdx.x * blockDim.x + threadIdx.x) >> 5);
    int lane = threadIdx.x & 31;
    const float4* src;
    uint2* dsth;
    float* dst;
    if (gw < NQ) {
        src = (const float4*)(X + (size_t)gw * F_DIM);
        dsth = (uint2*)(g_xh + (size_t)gw * F_DIM); dst = g_x2 + gw;
    } else if (gw < NQ + NA) {
        int r = gw - NQ;
        src = (const float4*)(Y + (size_t)r * F_DIM);
        dsth = (uint2*)(g_yh + (size_t)r * F_DIM); dst = g_y2 + r;
    } else return;
    float s = 0.f;
    #pragma unroll
    for (int k = 0; k < 2; k++) {
        int j = lane + k * 32;
        if (k == 0 || j < 40) {
            float4 v = src[j];
            s = fmaf(v.x, v.x, s); s = fmaf(v.y, v.y, s);
            s = fmaf(v.z, v.z, s); s = fmaf(v.w, v.w, s);
            __half2 h0 = __floats2half2_rn(v.x, v.y);
            __half2 h1 = __floats2half2_rn(v.z, v.w);
            uint2 u;
            u.x = *(uint32_t*)&h0; u.y = *(uint32_t*)&h1;
            dsth[j] = u;
        }
    }
    #pragma unroll
    for (int o = 16; o > 0; o >>= 1) s += __shfl_xor_sync(0xFFFFFFFFu, s, o);
    if (lane == 0) *dst = s;
}

// ---------------------------------------------------------------------------
// Kernel 1: fused scores(fp16 mma) -> weights as register A-fragments -> GEMM-2
// grid = 32 m-tiles x 32 A-splits; 256 threads; 2 CTAs/SM.
// GEMM-1 warp grid 4(m) x 2(n); warp tile 32x32. GEMM-2 done per-warp over
// its own 32-address window; nw halves reduced via smem at the end.
// ---------------------------------------------------------------------------
__global__ void __launch_bounds__(THREADS, 2) fused_kernel(
    const float* __restrict__ Mv)
{
    extern __shared__ __align__(1024) char sm[];
    const uint32_t sb = cvta_s(sm);
    const int tid  = threadIdx.x;
    const int lane = tid & 31, warp = tid >> 5;
    const int mw = warp >> 1, nw = warp & 1;
    const int g = lane >> 2, tig = lane & 3;
    const int m_tile = (int)blockIdx.x >> 5;
    const int split  = (int)blockIdx.x & (SPLITS - 1);
    const int a_start = split * A_CHUNK;

    // --- prologue: async-load Y tiles 0 and 1 ---------------------------
    issue_y(a_start, sb + OFF_Y0, tid); CPCOMMIT();
    issue_y(a_start + TN, sb + OFF_Y1, tid); CPCOMMIT();

    // --- X tile (fp16, once per CTA), x2 chunk, constant Mt rows --------
    {
        const char* xg = (const char*)(g_xh + (size_t)m_tile * 128 * F_DIM);
        #pragma unroll
        for (int k = 0; k < 10; k++) {
            int i = k * THREADS + tid;
            int r = i / 20, c = i - r * 20;
            *(uint4*)(sm + OFF_X + r * ROWB + c * 16) =
                *(const uint4*)(xg + (size_t)r * 320 + c * 16);
        }
    }
    if (tid < 128) ((float*)(sm + OFF_X2S))[tid] = g_x2[m_tile * 128 + tid];
    {   // Mt rows 10..15: ones column (den), zeros elsewhere (written once)
        __half one = __float2half(1.0f);
        __half zro = __float2half(0.0f);
        for (int i = tid; i < 6 * TN; i += THREADS) {
            int c = 10 + i / TN, j = i - (c - 10) * TN;
            *(__half*)(sm + OFF_MT + c * MTROWB + j * 2) = (c == 10) ? one : zro;
        }
    }
    __syncthreads();

    // --- per-thread ldmatrix bases --------------------------------------
    const int lrow = (lane & 7) + ((lane >> 3) & 1) * 8;
    const int lcol = ((lane >> 4) & 1) * 16;      // k 0-7 | 8-15 byte offset
    uint32_t aA[2];
    #pragma unroll
    for (int mf = 0; mf < 2; mf++)
        aA[mf] = sb + OFF_X + (mw * 32 + mf * 16 + lrow) * ROWB + lcol;
    uint32_t bBo[2];
    #pragma unroll
    for (int p = 0; p < 2; p++)
        bBo[p] = (uint32_t)((nw * 32 + p * 16 + lrow) * ROWB + lcol);
    const uint32_t bMb = sb + OFF_MT + lrow * MTROWB + lcol;

    float x2a[4];   // q = mf*2 + hi : row mw*32 + mf*16 + hi*8 + g
    {
        const float* x2s = (const float*)(sm + OFF_X2S);
        #pragma unroll
        for (int q = 0; q < 4; q++)
            x2a[q] = x2s[mw * 32 + (q >> 1) * 16 + (q & 1) * 8 + g];
    }

    float acc2[2][2][4];
    #pragma unroll
    for (int mf = 0; mf < 2; mf++)
        #pragma unroll
        for (int n = 0; n < 2; n++)
            #pragma unroll
            for (int q = 0; q < 4; q++) acc2[mf][n][q] = 0.f;
    float acc[2][4][4];

    for (int t = 0; t < NTILES; t++) {
        // prefetch next M tile (64x10) + y2 chunk into registers
        float mv[3];
        float y2v = 0.f;
        #pragma unroll
        for (int k = 0; k < 3; k++) {
            int i = k * THREADS + tid;
            if (i < TN * NC) {
                int j = i / 10, c = i - j * 10;
                mv[k] = Mv[(size_t)(a_start + t * TN + j) * NC + c];
            }
        }
        if (tid < TN) y2v = g_y2[a_start + t * TN + tid];
        #pragma unroll
        for (int mf = 0; mf < 2; mf++)
            #pragma unroll
            for (int nf = 0; nf < 4; nf++)
                #pragma unroll
                for (int q = 0; q < 4; q++) acc[mf][nf][q] = 0.f;

        CPWAIT1();              // Y buffer [t&1] ready
        __syncthreads();        // + prev epilogue/GEMM-2 done reading Mt/y2s

        // ---- GEMM-1: 10 fp16 K-steps (K=16 each), 8 MMA per step --------
        {
            const uint32_t yB = sb + OFF_Y0 + (t & 1) * SZ_YBUF;
            #pragma unroll
            for (int ks = 0; ks < 10; ks++) {
                uint32_t afr[2][4], bfr[2][4];
                #pragma unroll
                for (int mf = 0; mf < 2; mf++)
                    LDMX4(afr[mf], aA[mf] + ks * 32);
                #pragma unroll
                for (int p = 0; p < 2; p++)
                    LDMX4(bfr[p], yB + bBo[p] + ks * 32);
                #pragma unroll
                for (int mf = 0; mf < 2; mf++)
                    #pragma unroll
                    for (int p = 0; p < 2; p++) {
                        MMA_F16(acc[mf][p * 2],     afr[mf], bfr[p][0], bfr[p][2]);
                        MMA_F16(acc[mf][p * 2 + 1], afr[mf], bfr[p][1], bfr[p][3]);
                    }
            }
        }
        // publish Mt (fp16, transposed) + y2 chunk
        #pragma unroll
        for (int k = 0; k < 3; k++) {
            int i = k * THREADS + tid;
            if (i < TN * NC) {
                int j = i / 10, c = i - j * 10;
                *(__half*)(sm + OFF_MT + c * MTROWB + j * 2) = __float2half_rn(mv[k]);
            }
        }
        if (tid < TN) ((float*)(sm + OFF_Y2S))[tid] = y2v;
        __syncthreads();        // Y buf consumed; Mt/y2 visible

        if (t + 2 < NTILES) issue_y(a_start + (t + 2) * TN, sb + OFF_Y0 + (t & 1) * SZ_YBUF, tid);
        CPCOMMIT();

        // ---- fused epilogue + GEMM-2, all in registers -------------------
        // acc[mf][j2*2+hi] covers cols nw*32 + j2*16 + hi*8 + {2tig,2tig+1}
        // == exactly the m16n8k16 A-fragment (K = address axis).
        {
            const char* y2s = (const char*)(sm + OFF_Y2S);
            #pragma unroll
            for (int j2 = 0; j2 < 2; j2++) {
                const int cbase = nw * 32 + j2 * 16;
                uint32_t bm[4];
                LDMX4(bm, bMb + cbase * 2);
                float2 y2lo = *(const float2*)(y2s + (cbase + tig * 2) * 4);
                float2 y2hi = *(const float2*)(y2s + (cbase + 8 + tig * 2) * 4);
                #pragma unroll
                for (int mf = 0; mf < 2; mf++) {
                    uint32_t af[4];
                    af[0] = wpair2(acc[mf][j2 * 2][0],     acc[mf][j2 * 2][1],     x2a[mf * 2],     y2lo);
                    af[1] = wpair2(acc[mf][j2 * 2][2],     acc[mf][j2 * 2][3],     x2a[mf * 2 + 1], y2lo);
                    af[2] = wpair2(acc[mf][j2 * 2 + 1][0], acc[mf][j2 * 2 + 1][1], x2a[mf * 2],     y2hi);
                    af[3] = wpair2(acc[mf][j2 * 2 + 1][2], acc[mf][j2 * 2 + 1][3], x2a[mf * 2 + 1], y2hi);
                    MMA_F16(acc2[mf][0], af, bm[0], bm[2]);
                    MMA_F16(acc2[mf][1], af, bm[1], bm[3]);
                }
            }
        }
    }

    // --- reduce nw halves via smem, write per-split partials -------------
    __syncthreads();                       // everyone done with Y buffers
    float* red = (float*)(sm + OFF_Y0);    // scratch [4 mw][32 lane][16]
    if (nw == 1) {
        float* d = red + (mw * 32 + lane) * 16;
        #pragma unroll
        for (int mf = 0; mf < 2; mf++)
            #pragma unroll
            for (int n = 0; n < 2; n++)
                #pragma unroll
                for (int q = 0; q < 4; q++)
                    d[mf * 8 + n * 4 + q] = acc2[mf][n][q];
    }
    __syncthreads();
    if (nw == 0) {
        const float* s = red + (mw * 32 + lane) * 16;
        #pragma unroll
        for (int mf = 0; mf < 2; mf++) {
            int r0 = m_tile * 128 + mw * 32 + mf * 16 + g;
            size_t base = ((size_t)split * NQ + r0) * 16 + tig * 2;
            #pragma unroll
            for (int n = 0; n < 2; n++) {
                *(float2*)&g_part[base + n * 8] = make_float2(
                    acc2[mf][n][0] + s[mf * 8 + n * 4 + 0],
                    acc2[mf][n][1] + s[mf * 8 + n * 4 + 1]);
                *(float2*)&g_part[base + 8 * 16 + n * 8] = make_float2(
                    acc2[mf][n][2] + s[mf * 8 + n * 4 + 2],
                    acc2[mf][n][3] + s[mf * 8 + n * 4 + 3]);
            }
        }
    }
}

// ---------------------------------------------------------------------------
// Kernel 2: combine splits, normalize
// ---------------------------------------------------------------------------
__global__ void combine_kernel(float* __restrict__ out) {
    __shared__ float dsh[16];
    int tid = threadIdx.x;
    int il = tid >> 4, c = tid & 15;
    int i = blockIdx.x * 16 + il;
    float s = 0.f;
    #pragma unroll 4
    for (int sp = 0; sp < SPLITS; sp++)
        s += g_part[((size_t)sp * NQ + i) * 16 + c];
    if (c == 10) dsh[il] = s;
    __syncthreads();
    if (c < 10) out[(size_t)i * NC + c] = s / dsh[il];
}

// ---------------------------------------------------------------------------
// kernel_launch
// ---------------------------------------------------------------------------
extern "C" void kernel_launch(void* const* d_in, const int* in_sizes, int n_in,
                              void* d_out, int out_size) {
    const float* X  = (const float*)d_in[0];   // inputs  [4096, 160]
    const float* Y  = (const float*)d_in[1];   // Address [32768, 160]
    const float* Mv = (const float*)d_in[2];   // M       [32768, 10]
    float* out = (float*)d_out;                // [4096, 10]

    static bool attr_done = false;
    if (!attr_done) {
        cudaFuncSetAttribute(fused_kernel,
                             cudaFuncAttributeMaxDynamicSharedMemorySize, SMEM_BYTES);
        attr_done = true;
    }

    int norm_warps = NQ + NA;
    norms_kernel<<<(norm_warps * 32 + 255) / 256, 256>>>(X, Y);
    fused_kernel<<<(NQ / 128) * SPLITS, THREADS, SMEM_BYTES>>>(Mv);
    combine_kernel<<<NQ / 16, 256>>>(out);
}